// round 11
// baseline (speedup 1.0000x reference)
#include <cuda_runtime.h>

#define D_ 4
#define R_ 32
#define F_ 8
#define U_ 64
#define B_ 512

typedef unsigned long long ull;

// ---------- packed f32x2 helpers (SASS FFMA2) ----------
static __device__ __forceinline__ ull pk2(float lo, float hi) {
    ull r; asm("mov.b64 %0, {%1, %2};" : "=l"(r) : "f"(lo), "f"(hi)); return r;
}
static __device__ __forceinline__ void upk2(ull v, float& lo, float& hi) {
    asm("mov.b64 {%0, %1}, %2;" : "=f"(lo), "=f"(hi) : "l"(v));
}
static __device__ __forceinline__ ull fma2_(ull a, ull b, ull c) {
    ull d; asm("fma.rn.f32x2 %0, %1, %2, %3;" : "=l"(d) : "l"(a), "l"(b), "l"(c)); return d;
}
static __device__ __forceinline__ ull mul2_(ull a, ull b) {
    ull d; asm("mul.rn.f32x2 %0, %1, %2;" : "=l"(d) : "l"(a), "l"(b)); return d;
}
static __device__ __forceinline__ ull add2_(ull a, ull b) {
    ull d; asm("add.rn.f32x2 %0, %1, %2;" : "=l"(d) : "l"(a), "l"(b)); return d;
}

// Pair-merged products: g_KK[u][p][c=(d0*4+d1)][j*32+k], and its transpose
// g_KKT[u][p][c][k*32+j].
__device__ float g_KK [U_ * 4 * 16 * 1024];   // 16 MB
__device__ float g_KKT[U_ * 4 * 16 * 1024];   // 16 MB

// ---------------------------------------------------------------------------
// Precompute: 512 blocks = (u, p, half), 256 threads = 8 warps; warp w
// computes c = 8*half + w. Stages 2 A-matrices (d0 in {2h, 2h+1}) and 4
// B-matrices. 2x wave-parallelism vs the 256-block version.
// ---------------------------------------------------------------------------
__global__ __launch_bounds__(256) void kk_precompute(const float* __restrict__ K) {
    extern __shared__ float ps[];
    float* As = ps;            // 2 * 1056 (pitch 33)
    float* Bs = ps + 2112;     // 4 * 1024
    float* Ts = ps + 6208;     // 8 * 1056 (per-warp transpose staging)
    const int u = blockIdx.x >> 3;
    const int p = (blockIdx.x >> 1) & 3;
    const int h = blockIdx.x & 1;
    const int tid = threadIdx.x;

    for (int a = 0; a < 2; a++)
        for (int e = tid; e < 1024; e += 256)
            As[a * 1056 + (e >> 5) * 33 + (e & 31)] =
                K[(((2 * h + a) * 1024 + e) * 8 + 2 * p) * 64 + u];
    for (int d = 0; d < 4; d++)
        for (int e = tid; e < 1024; e += 256)
            Bs[d * 1024 + e] = K[((d * 1024 + e) * 8 + 2 * p + 1) * 64 + u];
    __syncthreads();

    const int w = tid >> 5, lane = tid & 31;
    const int c = 8 * h + w;
    const int a0 = w >> 2, d1 = w & 3;
    ull acc[16];
    #pragma unroll
    for (int q = 0; q < 16; q++) acc[q] = 0ull;
    const float* arow = &As[a0 * 1056 + lane * 33];
    const ulonglong2* bmat = (const ulonglong2*)(Bs + d1 * 1024);
    #pragma unroll
    for (int j = 0; j < 32; j++) {
        const ull a2 = pk2(arow[j], arow[j]);
        #pragma unroll
        for (int q = 0; q < 8; q++) {
            const ulonglong2 bv = bmat[j * 8 + q];   // broadcast
            acc[2 * q]     = fma2_(a2, bv.x, acc[2 * q]);
            acc[2 * q + 1] = fma2_(a2, bv.y, acc[2 * q + 1]);
        }
    }
    // unpack row, write KK row-major (lane = row)
    float f[32];
    #pragma unroll
    for (int q = 0; q < 16; q++) upk2(acc[q], f[2 * q], f[2 * q + 1]);
    {
        float4* dst = (float4*)(g_KK + (((u * 4 + p) * 16 + c) * 1024) + lane * 32);
        #pragma unroll
        for (int q = 0; q < 8; q++) {
            float4 o; o.x = f[4*q]; o.y = f[4*q+1]; o.z = f[4*q+2]; o.w = f[4*q+3];
            dst[q] = o;
        }
    }
    // transpose via smem staging (pitch 33, conflict-free both directions)
    float* Tw = Ts + w * 1056;
    #pragma unroll
    for (int k = 0; k < 32; k++) Tw[lane * 33 + k] = f[k];
    __syncwarp();
    float* kt = g_KKT + (((u * 4 + p) * 16 + c) * 1024);
    #pragma unroll
    for (int i = 0; i < 32; i++)
        kt[i * 32 + lane] = Tw[lane * 33 + i];
}

// ---------------------------------------------------------------------------
// Main. Block = 256 threads = 8 warps, one u, 8 b (warp w owns b = b0+w).
// Smem (floats): W[512] | SL[8*1152] | SR[8*1152] | SC[8*1152]
//   = 112.6 KB per CTA -> 2 CTAs/SM.
// Fully software-pipelined: every kk register-set load is issued behind
// prior compute; builds are pure register FFMA2.
//   load kk0,kk1 | W | sync0 | build S0(kk0)->SL | load kk2 | build S1(kk1)->SR
//   | load kk3 | sync1 | build S2T(kk2)->SC | mm1(SL,SR)->acc1 | sync2
//   | build S3T(kk3)->SL | sync3 | mm2(SL,SC) + trace
// ---------------------------------------------------------------------------
#define PITCH 36
#define SLOT  1152
#define OFF_SL  512
#define OFF_SR  (OFF_SL + 8 * SLOT)
#define OFF_SC  (OFF_SR + 8 * SLOT)
#define SMEM_FLOATS (OFF_SC + 8 * SLOT)

static __device__ __forceinline__ void load_kk(const float* src, int e,
                                               ulonglong2 kk[16]) {
    const ulonglong2* base = (const ulonglong2*)src;
    #pragma unroll
    for (int c = 0; c < 16; c++) kk[c] = base[c * 256 + e];   // coalesced LDG.128
}

// Build one stage for all 8 b's from register-resident kk; thread e owns
// element (j = e>>3, 4 k's). 4 independent fma2 chains per b.
static __device__ __forceinline__ void build_from(const ulonglong2 kk[16],
                                                  int p, int e,
                                                  const float* Wsm, float* dst) {
    const int j = e >> 3, k4 = e & 7;
    #pragma unroll 2
    for (int b = 0; b < 8; b++) {
        const float4* wp = (const float4*)(Wsm + (b * 4 + p) * 16);
        const float4 wa = wp[0], wb = wp[1], wc = wp[2], wd = wp[3];  // broadcast
        const ull q0 = pk2(wa.x, wa.x), q1 = pk2(wa.y, wa.y);
        const ull q2 = pk2(wa.z, wa.z), q3 = pk2(wa.w, wa.w);
        const ull q4 = pk2(wb.x, wb.x), q5 = pk2(wb.y, wb.y);
        const ull q6 = pk2(wb.z, wb.z), q7 = pk2(wb.w, wb.w);
        const ull q8 = pk2(wc.x, wc.x), q9 = pk2(wc.y, wc.y);
        const ull qa = pk2(wc.z, wc.z), qb = pk2(wc.w, wc.w);
        const ull qc = pk2(wd.x, wd.x), qd = pk2(wd.y, wd.y);
        const ull qe = pk2(wd.z, wd.z), qf = pk2(wd.w, wd.w);
        ull ax0 = mul2_(q0, kk[0].x),  ay0 = mul2_(q0, kk[0].y);
        ull ax1 = mul2_(q1, kk[1].x),  ay1 = mul2_(q1, kk[1].y);
        ax0 = fma2_(q2, kk[2].x, ax0); ay0 = fma2_(q2, kk[2].y, ay0);
        ax1 = fma2_(q3, kk[3].x, ax1); ay1 = fma2_(q3, kk[3].y, ay1);
        ax0 = fma2_(q4, kk[4].x, ax0); ay0 = fma2_(q4, kk[4].y, ay0);
        ax1 = fma2_(q5, kk[5].x, ax1); ay1 = fma2_(q5, kk[5].y, ay1);
        ax0 = fma2_(q6, kk[6].x, ax0); ay0 = fma2_(q6, kk[6].y, ay0);
        ax1 = fma2_(q7, kk[7].x, ax1); ay1 = fma2_(q7, kk[7].y, ay1);
        ax0 = fma2_(q8, kk[8].x, ax0); ay0 = fma2_(q8, kk[8].y, ay0);
        ax1 = fma2_(q9, kk[9].x, ax1); ay1 = fma2_(q9, kk[9].y, ay1);
        ax0 = fma2_(qa, kk[10].x, ax0); ay0 = fma2_(qa, kk[10].y, ay0);
        ax1 = fma2_(qb, kk[11].x, ax1); ay1 = fma2_(qb, kk[11].y, ay1);
        ax0 = fma2_(qc, kk[12].x, ax0); ay0 = fma2_(qc, kk[12].y, ay0);
        ax1 = fma2_(qd, kk[13].x, ax1); ay1 = fma2_(qd, kk[13].y, ay1);
        ax0 = fma2_(qe, kk[14].x, ax0); ay0 = fma2_(qe, kk[14].y, ay0);
        ax1 = fma2_(qf, kk[15].x, ax1); ay1 = fma2_(qf, kk[15].y, ay1);
        const ull sx = add2_(ax0, ax1), sy = add2_(ay0, ay1);
        float4 o;
        upk2(sx, o.x, o.y); upk2(sy, o.z, o.w);
        *(float4*)(dst + b * SLOT + j * PITCH + 4 * k4) = o;
    }
}

// Register-tiled 32x32x32 matmul: C = A @ B, operands pitch-36 in smem.
// Lane (r = lane>>2, c = lane&3): rows {r,r+8,r+16,r+24} x cols {8c..8c+7}.
static __device__ __forceinline__ void mmk(const float* A, const float* B,
                                           int r, int c, ull acc[16]) {
    #pragma unroll
    for (int i = 0; i < 16; i++) acc[i] = 0ull;
    #pragma unroll
    for (int k4 = 0; k4 < 8; k4++) {
        float4 av[4];
        #pragma unroll
        for (int rho = 0; rho < 4; rho++)
            av[rho] = *(const float4*)(A + (r + 8 * rho) * PITCH + 4 * k4);
        ulonglong2 bv[4][2];
        #pragma unroll
        for (int kp = 0; kp < 4; kp++) {
            bv[kp][0] = *(const ulonglong2*)(B + (4 * k4 + kp) * PITCH + 8 * c);
            bv[kp][1] = *(const ulonglong2*)(B + (4 * k4 + kp) * PITCH + 8 * c + 4);
        }
        #pragma unroll
        for (int rho = 0; rho < 4; rho++) {
            const float* af = (const float*)&av[rho];
            #pragma unroll
            for (int kp = 0; kp < 4; kp++) {
                const ull a2 = pk2(af[kp], af[kp]);
                acc[rho * 4 + 0] = fma2_(a2, bv[kp][0].x, acc[rho * 4 + 0]);
                acc[rho * 4 + 1] = fma2_(a2, bv[kp][0].y, acc[rho * 4 + 1]);
                acc[rho * 4 + 2] = fma2_(a2, bv[kp][1].x, acc[rho * 4 + 2]);
                acc[rho * 4 + 3] = fma2_(a2, bv[kp][1].y, acc[rho * 4 + 3]);
            }
        }
    }
}

__global__ __launch_bounds__(256, 2) void ring_main(const float* __restrict__ X,
                                                    float* __restrict__ out) {
    extern __shared__ float smem[];
    float* Wsm = smem;
    float* SL  = smem + OFF_SL;
    float* SR  = smem + OFF_SR;
    float* SC  = smem + OFF_SC;

    const int tid = threadIdx.x, w = tid >> 5, lane = tid & 31;
    const int r = lane >> 2, c = lane & 3;
    const int u = blockIdx.x >> 6;
    const int b0 = (blockIdx.x & 63) * 8;

    // ---- prefetch kk0/kk1 (LDG latency hidden behind W + sync0)
    ulonglong2 kkA[16], kkB[16];
    load_kk(g_KK + (size_t)((u * 4 + 0) * 16) * 1024, tid, kkA);
    load_kk(g_KK + (size_t)((u * 4 + 1) * 16) * 1024, tid, kkB);

    // W[b][p][c=(d0,d1)] = x[2p,d0] * x[2p+1,d1], straight from global X
    #pragma unroll
    for (int i = tid; i < 512; i += 256) {
        const int bb = i >> 6, pp = (i >> 4) & 3, cc = i & 15;
        Wsm[i] = X[(b0 + bb) * 32 + 8 * pp + (cc >> 2)] *
                 X[(b0 + bb) * 32 + 8 * pp + 4 + (cc & 3)];
    }
    __syncthreads();

    // ---- phase 1 builds; kk2/kk3 loads reuse the dead kkA/kkB registers
    build_from(kkA, 0, tid, Wsm, SL);
    load_kk(g_KKT + (size_t)((u * 4 + 2) * 16) * 1024, tid, kkA);
    build_from(kkB, 1, tid, Wsm, SR);
    load_kk(g_KKT + (size_t)((u * 4 + 3) * 16) * 1024, tid, kkB);
    __syncthreads();

    // ---- build S2T into SC (register-resident kk2), then mm1
    build_from(kkA, 2, tid, Wsm, SC);
    ull acc1[16];
    mmk(SL + w * SLOT, SR + w * SLOT, r, c, acc1);
    __syncthreads();   // mm1 reads of SL done; SC writes complete

    // ---- build S3T into SL (register-resident kk3)
    build_from(kkB, 3, tid, Wsm, SL);
    __syncthreads();

    // ---- mm2: BT = S3T @ S2T = (S2 S3)^T ; out = sum A .* BT
    {
        ull acc2[16];
        mmk(SL + w * SLOT, SC + w * SLOT, r, c, acc2);
        ull t = 0ull;
        #pragma unroll
        for (int i = 0; i < 16; i++) t = fma2_(acc1[i], acc2[i], t);
        float tl, th; upk2(t, tl, th);
        float pacc = tl + th;
        #pragma unroll
        for (int o = 16; o; o >>= 1)
            pacc += __shfl_xor_sync(0xffffffffu, pacc, o);
        if (lane == 0) out[(b0 + w) * 64 + u] = pacc;
    }
}

extern "C" void kernel_launch(void* const* d_in, const int* in_sizes, int n_in,
                              void* d_out, int out_size) {
    const float* X = (const float*)d_in[0];
    const float* K = (const float*)d_in[1];
    if (in_sizes[0] != B_ * F_ * D_) {
        X = (const float*)d_in[1];
        K = (const float*)d_in[0];
    }
    const int pre_smem = (2112 + 4096 + 8448) * 4;
    cudaFuncSetAttribute(kk_precompute, cudaFuncAttributeMaxDynamicSharedMemorySize,
                         pre_smem);
    cudaFuncSetAttribute(ring_main, cudaFuncAttributeMaxDynamicSharedMemorySize,
                         SMEM_FLOATS * 4);
    kk_precompute<<<512, 256, pre_smem>>>(K);
    ring_main<<<64 * 64, 256, SMEM_FLOATS * 4>>>(X, (float*)d_out);
}